// round 12
// baseline (speedup 1.0000x reference)
#include <cuda_runtime.h>
#include <cuda_bf16.h>
#include <cstdint>
#include <math.h>

#define EDIM   512
#define TSTEPS 8
#define NWIN   8192
#define XROWS  65536
#define KSTORE 1024            // A/H stored int8: [limb1(512) | limb0(512)]
#define KSPLIT 1536            // W stored int8:  [w1(512) | w0(512) | w1(512)]
#define NKIT   24              // 1536 int8-K / 64 per chunk
#define ROWB   80              // smem row stride (64B data + 16B pad)
#define ATILEB (64 * ROWB)     // 5120   (A: 64 rows)
#define BTILEB (128 * ROWB)    // 10240  (B: 128 rows)
#define STAGEB (ATILEB + BTILEB)   // 15360
#define NSTAGE 3
#define SMEMB  (NSTAGE * STAGEB)   // 46080  (x4 CTAs = 184320 <= 227KB)

#define SC_PROJ (1.0f / 4194304.0f)    // 2^-11 * 2^-18 * 128
#define SC_REC  (1.0f / 33554432.0f)   // 2^-14 * 2^-18 * 128

// ---------------- scratch ----------------------------------------------------
__device__ int8_t g_xs[(size_t)XROWS * KSTORE];      // 67 MB
__device__ int8_t g_ws[2][(size_t)EDIM * KSPLIT];    // 2 x 0.75 MB
__device__ int8_t g_hs[2][(size_t)NWIN * KSTORE];    // 2 x 8.4 MB
__device__ float  g_pre[(size_t)XROWS * EDIM];       // 134 MB

// ---------------- helpers ----------------------------------------------------
__device__ __forceinline__ uint32_t smem_u32(const void* p) {
    uint32_t a;
    asm("{ .reg .u64 t; cvta.to.shared.u64 t, %1; cvt.u32.u64 %0, t; }"
        : "=r"(a) : "l"(p));
    return a;
}
__device__ __forceinline__ void cp16(uint32_t saddr, const void* gaddr) {
    asm volatile("cp.async.cg.shared.global [%0], [%1], 16;"
                 :: "r"(saddr), "l"(gaddr) : "memory");
}
__device__ __forceinline__ void cp_commit() {
    asm volatile("cp.async.commit_group;" ::: "memory");
}
template <int N>
__device__ __forceinline__ void cp_wait() {
    asm volatile("cp.async.wait_group %0;" :: "n"(N) : "memory");
}
__device__ __forceinline__ void ldsm4(uint32_t& r0, uint32_t& r1, uint32_t& r2,
                                      uint32_t& r3, uint32_t addr) {
    asm volatile("ldmatrix.sync.aligned.m8n8.x4.shared.b16 {%0,%1,%2,%3}, [%4];"
                 : "=r"(r0), "=r"(r1), "=r"(r2), "=r"(r3) : "r"(addr));
}
__device__ __forceinline__ void mma16832(int32_t* c, const uint32_t* a,
                                         uint32_t b0, uint32_t b1) {
    asm volatile("mma.sync.aligned.m16n8k32.row.col.s32.s8.s8.s32 "
                 "{%0,%1,%2,%3}, {%4,%5,%6,%7}, {%8,%9}, {%0,%1,%2,%3};"
                 : "+r"(c[0]), "+r"(c[1]), "+r"(c[2]), "+r"(c[3])
                 : "r"(a[0]), "r"(a[1]), "r"(a[2]), "r"(a[3]), "r"(b0), "r"(b1));
}
// Rounded fixed-point split: v*scale -> 15-bit int -> two int8 limbs,
// residual in [-64, 63] (zero-mean).
__device__ __forceinline__ void quant15(float v, float scale, int8_t& hi, int8_t& lo) {
    int xi = __float2int_rn(v * scale);
    xi = max(-16320, min(16319, xi));
    int h = (xi + 64) >> 7;
    hi = (int8_t)h;
    lo = (int8_t)(xi - (h << 7));
}

// ---------------- prep kernels ----------------------------------------------
__global__ __launch_bounds__(256)
void prep_w(const float* __restrict__ wih, const float* __restrict__ whh) {
    int idx = blockIdx.x * 256 + threadIdx.x;           // 0 .. 2*512*512-1
    int which = idx >> 18;
    int e = idx & 262143;
    int n = e >> 9, k = e & 511;
    const float* src = which ? whh : wih;
    int8_t w1, w0;
    quant15(src[n * 512 + k], 262144.0f, w1, w0);       // 2^18
    int8_t* dst = g_ws[which] + (size_t)n * KSPLIT;
    dst[k] = w1; dst[512 + k] = w0; dst[1024 + k] = w1;
}

__global__ __launch_bounds__(256)
void prep_x(const float* __restrict__ x) {
    size_t idx = (size_t)blockIdx.x * 256 + threadIdx.x;  // 65536*128 float4
    size_t row = idx >> 7;
    int q = (int)(idx & 127);
    float4 v = ((const float4*)x)[idx];
    int8_t h0,h1,h2,h3,l0,l1,l2,l3;
    quant15(v.x, 2048.0f, h0, l0);                      // 2^11
    quant15(v.y, 2048.0f, h1, l1);
    quant15(v.z, 2048.0f, h2, l2);
    quant15(v.w, 2048.0f, h3, l3);
    int8_t* base = g_xs + row * KSTORE + q * 4;
    *(char4*)(base)       = make_char4(h0, h1, h2, h3);
    *(char4*)(base + 512) = make_char4(l0, l1, l2, l3);
}

// ---------------- int8 split GEMM (64x128 tile, 128 thr, 4 CTAs/SM) ----------
// Single accumulator with a phase fold:
//   chunks 0..7  : acc += a1*w1           (D1)
//   after c==7   : acc *= 128             (fold; |acc|<1.06e9, no overflow)
//   chunks 8..23 : acc += a1*w0 + a0*w1   (D2)
// dot = sc * acc
// A chunk byte-offset: (c<8 ? c : c-8)*64  ([limb1|limb0] layout)
// mode 0: g_pre = dot + bias; t=0 rows also write quantized H0
// mode 1: h = tanh(dot + pre_t); quantized h out (fp32 out at t=7)
__global__ __launch_bounds__(128, 4)
void gemm_s8x3(const int8_t* __restrict__ A,
               const int8_t* __restrict__ Bw,
               const float* __restrict__ b0, const float* __restrict__ b1,
               float* __restrict__ outp, int8_t* __restrict__ hs_out,
               int8_t* __restrict__ h0_out,
               float sc, int mode, int t)
{
    extern __shared__ __align__(16) char dyn[];   // NSTAGE x [A:5120 | B:10240]
    __shared__ float s_bias[128];

    const int tid = threadIdx.x;
    const int wid = tid >> 5;
    const int lane = tid & 31;
    const int warpM = wid & 1;            // 2 warps along M (32 each)
    const int warpN = wid >> 1;           // 2 warps along N (64 each)
    const int bm = blockIdx.y * 64;
    const int bn = blockIdx.x * 128;

    const uint32_t sbase = smem_u32(dyn);

    if (mode == 0 && tid < 128) s_bias[tid] = b0[bn + tid] + b1[bn + tid];

    // Loaders: A tile 64x64B = 256 u4 (2/thread, CONSECUTIVE); B tile 128x64B
    // = 512 u4 (4/thread).
    const int a_row = tid >> 1;             // 0..63
    const int a_c   = (tid & 1) * 2;        // u4 index 0 or 2
    const int b_row = tid;                  // 0..127
    const uint4* A4 = (const uint4*)A;      // row stride 64 uint4 (1024 B)
    const uint4* B4 = (const uint4*)Bw;     // row stride 96 uint4 (1536 B)

    const uint32_t sA = a_row * ROWB + a_c * 16;
    const uint32_t sB = b_row * ROWB;
    const uint4* Ap = &A4[(size_t)(bm + a_row) * 64 + a_c];
    const uint4* Bp = &B4[(size_t)(bn + b_row) * 96];

    // ldmatrix lane offsets
    const int g = lane >> 3;
    uint32_t a_off[2], b_off[4];
    #pragma unroll
    for (int mt = 0; mt < 2; mt++)
        a_off[mt] = (uint32_t)((warpM * 32 + mt * 16 + (g & 1) * 8 + (lane & 7)) * ROWB
                               + (g >> 1) * 16);
    #pragma unroll
    for (int np = 0; np < 4; np++)
        b_off[np] = (uint32_t)((warpN * 64 + np * 16 + (g >> 1) * 8 + (lane & 7)) * ROWB
                               + (g & 1) * 16);

    int32_t acc[2][8][4];
    #pragma unroll
    for (int i = 0; i < 2; i++)
        #pragma unroll
        for (int j = 0; j < 8; j++)
            #pragma unroll
            for (int q = 0; q < 4; q++) acc[i][j][q] = 0;

    // ---- prologue: fill stages 0..NSTAGE-2 (chunks 0..1, all < 8)
    #pragma unroll
    for (int s = 0; s < NSTAGE - 1; s++) {
        const uint32_t st = sbase + s * STAGEB;
        cp16(st + sA,      Ap + s * 4);          // bytes [a_c*16, a_c*16+16)
        cp16(st + sA + 16, Ap + s * 4 + 1);      // bytes [a_c*16+16, a_c*16+32)
        #pragma unroll
        for (int j = 0; j < 4; j++)
            cp16(st + ATILEB + sB + j * 16, Bp + s * 4 + j);
        cp_commit();
    }

    int st_cur = 0, st_nxt = NSTAGE - 1;
    for (int c = 0; c < NKIT; c++) {
        cp_wait<NSTAGE - 2>();
        __syncthreads();

        const int cn = c + NSTAGE - 1;
        if (cn < NKIT) {
            const uint32_t st = sbase + st_nxt * STAGEB;
            const int ka = (cn < 8 ? cn : cn - 8) * 4;
            cp16(st + sA,      Ap + ka);
            cp16(st + sA + 16, Ap + ka + 1);
            #pragma unroll
            for (int j = 0; j < 4; j++)
                cp16(st + ATILEB + sB + j * 16, Bp + cn * 4 + j);
        }
        cp_commit();
        if (++st_nxt == NSTAGE) st_nxt = 0;

        const uint32_t ab = sbase + st_cur * STAGEB;
        const uint32_t bb = ab + ATILEB;
        if (++st_cur == NSTAGE) st_cur = 0;

        #pragma unroll
        for (int kk = 0; kk < 2; kk++) {
            uint32_t afr[2][4];
            uint32_t bfr[4][4];
            #pragma unroll
            for (int mt = 0; mt < 2; mt++)
                ldsm4(afr[mt][0], afr[mt][1], afr[mt][2], afr[mt][3],
                      ab + a_off[mt] + kk * 32);
            #pragma unroll
            for (int np = 0; np < 4; np++)
                ldsm4(bfr[np][0], bfr[np][1], bfr[np][2], bfr[np][3],
                      bb + b_off[np] + kk * 32);
            #pragma unroll
            for (int np = 0; np < 4; np++)
                #pragma unroll
                for (int mt = 0; mt < 2; mt++) {
                    mma16832(acc[mt][np * 2],     afr[mt], bfr[np][0], bfr[np][1]);
                    mma16832(acc[mt][np * 2 + 1], afr[mt], bfr[np][2], bfr[np][3]);
                }
        }

        if (c == 7) {   // phase fold: D1 complete -> scale by 128, continue with D2
            #pragma unroll
            for (int i = 0; i < 2; i++)
                #pragma unroll
                for (int j = 0; j < 8; j++)
                    #pragma unroll
                    for (int q = 0; q < 4; q++) acc[i][j][q] *= 128;
        }
    }

    // ---- epilogue --------------------------------------------------------
    const int r_in = lane >> 2;
    const int c_in = (lane & 3) * 2;
    #pragma unroll
    for (int mt = 0; mt < 2; mt++) {
        const int m0 = bm + warpM * 32 + mt * 16 + r_in;   // and m0+8
        #pragma unroll
        for (int nt = 0; nt < 8; nt++) {
            const int nb = bn + warpN * 64 + nt * 8 + c_in;
            float v00 = (float)acc[mt][nt][0] * sc;
            float v01 = (float)acc[mt][nt][1] * sc;
            float v10 = (float)acc[mt][nt][2] * sc;
            float v11 = (float)acc[mt][nt][3] * sc;
            if (mode == 0) {
                const float bia0 = s_bias[nb - bn], bia1 = s_bias[nb - bn + 1];
                v00 += bia0; v01 += bia1; v10 += bia0; v11 += bia1;
                *(float2*)(g_pre + (size_t)m0 * EDIM + nb)       = make_float2(v00, v01);
                *(float2*)(g_pre + (size_t)(m0 + 8) * EDIM + nb) = make_float2(v10, v11);
                if ((m0 & 7) == 0) {
                    #pragma unroll
                    for (int h = 0; h < 2; h++) {
                        const size_t w = (size_t)(m0 + 8 * h) >> 3;
                        float a0 = tanhf(h ? v10 : v00);
                        float a1 = tanhf(h ? v11 : v01);
                        int8_t x0,x1,y0,y1;
                        quant15(a0, 16384.0f, x0, y0);
                        quant15(a1, 16384.0f, x1, y1);
                        int8_t* hd = h0_out + w * KSTORE + nb;
                        *(char2*)(hd)       = make_char2(x0, x1);
                        *(char2*)(hd + 512) = make_char2(y0, y1);
                    }
                }
            } else {
                #pragma unroll
                for (int h = 0; h < 2; h++) {
                    const int m = m0 + 8 * h;
                    float2 pr = *(const float2*)(g_pre + ((size_t)m * TSTEPS + t) * EDIM + nb);
                    float a0 = tanhf((h ? v10 : v00) + pr.x);
                    float a1 = tanhf((h ? v11 : v01) + pr.y);
                    if (t == TSTEPS - 1) {
                        *(float2*)(outp + (size_t)m * EDIM + nb) = make_float2(a0, a1);
                    } else {
                        int8_t x0,x1,y0,y1;
                        quant15(a0, 16384.0f, x0, y0);
                        quant15(a1, 16384.0f, x1, y1);
                        int8_t* hd = hs_out + (size_t)m * KSTORE + nb;
                        *(char2*)(hd)       = make_char2(x0, x1);
                        *(char2*)(hd + 512) = make_char2(y0, y1);
                    }
                }
            }
        }
    }
}

// ---------------- host ------------------------------------------------------
extern "C" void kernel_launch(void* const* d_in, const int* in_sizes, int n_in,
                              void* d_out, int out_size)
{
    (void)in_sizes; (void)n_in; (void)out_size;
    const float* x    = (const float*)d_in[0];
    const float* W_ih = (const float*)d_in[1];
    const float* W_hh = (const float*)d_in[2];
    const float* b_ih = (const float*)d_in[3];
    const float* b_hh = (const float*)d_in[4];
    float* out = (float*)d_out;

    static int8_t* p_xs = nullptr;
    static int8_t* p_ws[2];
    static int8_t* p_hs[2];
    if (!p_xs) {
        void* p;
        cudaGetSymbolAddress(&p, g_xs); p_xs = (int8_t*)p;
        cudaGetSymbolAddress(&p, g_ws);
        p_ws[0] = (int8_t*)p;
        p_ws[1] = p_ws[0] + (size_t)EDIM * KSPLIT;
        cudaGetSymbolAddress(&p, g_hs);
        p_hs[0] = (int8_t*)p;
        p_hs[1] = p_hs[0] + (size_t)NWIN * KSTORE;
        cudaFuncSetAttribute(gemm_s8x3,
                             cudaFuncAttributeMaxDynamicSharedMemorySize, SMEMB);
    }

    prep_w<<<2048, 256>>>(W_ih, W_hh);
    prep_x<<<32768, 256>>>(x);

    // pre = X @ Wih^T + bias ; fused quantized H0 for t=0 rows
    gemm_s8x3<<<dim3(4, 1024), 128, SMEMB>>>(p_xs, p_ws[0], b_ih, b_hh,
                                             nullptr, nullptr, p_hs[0],
                                             SC_PROJ, 0, 0);

    // recurrence: grid 512 CTAs <= 592 occ-4 slots -> single wave
    for (int t = 1; t < TSTEPS; t++) {
        gemm_s8x3<<<dim3(4, 128), 128, SMEMB>>>(
            p_hs[(t - 1) & 1], p_ws[1], nullptr, nullptr,
            (t == TSTEPS - 1) ? out : nullptr, p_hs[t & 1], nullptr,
            SC_REC, 1, t);
    }
}

// round 14
// speedup vs baseline: 1.4342x; 1.4342x over previous
#include <cuda_runtime.h>
#include <cuda_bf16.h>
#include <cstdint>
#include <math.h>

#define EDIM   512
#define TSTEPS 8
#define NWIN   8192
#define XROWS  65536
#define KSTORE 1024            // A/H stored int8: [limb1(512) | limb0(512)]
#define KSPLIT 1536            // W stored int8:  [w1(512) | w0(512) | w1(512)]
#define NKIT   24              // 1536 int8-K / 64 per chunk
#define ROWB   80              // smem row stride (64B data + 16B pad)
#define ATILEB (128 * ROWB)    // 10240
#define BTILEB (64 * ROWB)     // 5120
#define STAGEB (ATILEB + BTILEB)   // 15360
#define NSTAGE 4
#define SMEMB  (NSTAGE * STAGEB)   // 61440  (x3 CTAs = 184320)

#define SC_PROJ (1.0f / 4194304.0f)    // 2^-11 * 2^-18 * 128
#define SC_REC  (1.0f / 33554432.0f)   // 2^-14 * 2^-18 * 128

// ---------------- scratch ----------------------------------------------------
__device__ int8_t g_xs[(size_t)XROWS * KSTORE];      // 67 MB
__device__ int8_t g_ws[2][(size_t)EDIM * KSPLIT];    // 2 x 0.75 MB
__device__ int8_t g_hs[2][(size_t)NWIN * KSTORE];    // 2 x 8.4 MB
__device__ float  g_pre[(size_t)XROWS * EDIM];       // 134 MB

// ---------------- helpers ----------------------------------------------------
__device__ __forceinline__ uint32_t smem_u32(const void* p) {
    uint32_t a;
    asm("{ .reg .u64 t; cvta.to.shared.u64 t, %1; cvt.u32.u64 %0, t; }"
        : "=r"(a) : "l"(p));
    return a;
}
__device__ __forceinline__ void cp16(uint32_t saddr, const void* gaddr) {
    asm volatile("cp.async.cg.shared.global [%0], [%1], 16;"
                 :: "r"(saddr), "l"(gaddr) : "memory");
}
__device__ __forceinline__ void cp_commit() {
    asm volatile("cp.async.commit_group;" ::: "memory");
}
template <int N>
__device__ __forceinline__ void cp_wait() {
    asm volatile("cp.async.wait_group %0;" :: "n"(N) : "memory");
}
__device__ __forceinline__ void ldsm4(uint32_t& r0, uint32_t& r1, uint32_t& r2,
                                      uint32_t& r3, uint32_t addr) {
    asm volatile("ldmatrix.sync.aligned.m8n8.x4.shared.b16 {%0,%1,%2,%3}, [%4];"
                 : "=r"(r0), "=r"(r1), "=r"(r2), "=r"(r3) : "r"(addr));
}
__device__ __forceinline__ void mma16832(int32_t* c, const uint32_t* a,
                                         uint32_t b0, uint32_t b1) {
    asm volatile("mma.sync.aligned.m16n8k32.row.col.s32.s8.s8.s32 "
                 "{%0,%1,%2,%3}, {%4,%5,%6,%7}, {%8,%9}, {%0,%1,%2,%3};"
                 : "+r"(c[0]), "+r"(c[1]), "+r"(c[2]), "+r"(c[3])
                 : "r"(a[0]), "r"(a[1]), "r"(a[2]), "r"(a[3]), "r"(b0), "r"(b1));
}
// Rounded fixed-point split: v*scale -> 15-bit int -> two int8 limbs,
// residual in [-64, 63] (zero-mean).
__device__ __forceinline__ void quant15(float v, float scale, int8_t& hi, int8_t& lo) {
    int xi = __float2int_rn(v * scale);
    xi = max(-16320, min(16319, xi));
    int h = (xi + 64) >> 7;
    hi = (int8_t)h;
    lo = (int8_t)(xi - (h << 7));
}

// ---------------- prep kernels ----------------------------------------------
__global__ __launch_bounds__(256)
void prep_w(const float* __restrict__ wih, const float* __restrict__ whh) {
    int idx = blockIdx.x * 256 + threadIdx.x;           // 0 .. 2*512*512-1
    int which = idx >> 18;
    int e = idx & 262143;
    int n = e >> 9, k = e & 511;
    const float* src = which ? whh : wih;
    int8_t w1, w0;
    quant15(src[n * 512 + k], 262144.0f, w1, w0);       // 2^18
    int8_t* dst = g_ws[which] + (size_t)n * KSPLIT;
    dst[k] = w1; dst[512 + k] = w0; dst[1024 + k] = w1;
}

__global__ __launch_bounds__(256)
void prep_x(const float* __restrict__ x) {
    size_t idx = (size_t)blockIdx.x * 256 + threadIdx.x;  // 65536*128 float4
    size_t row = idx >> 7;
    int q = (int)(idx & 127);
    float4 v = ((const float4*)x)[idx];
    int8_t h0,h1,h2,h3,l0,l1,l2,l3;
    quant15(v.x, 2048.0f, h0, l0);                      // 2^11
    quant15(v.y, 2048.0f, h1, l1);
    quant15(v.z, 2048.0f, h2, l2);
    quant15(v.w, 2048.0f, h3, l3);
    int8_t* base = g_xs + row * KSTORE + q * 4;
    *(char4*)(base)       = make_char4(h0, h1, h2, h3);
    *(char4*)(base + 512) = make_char4(l0, l1, l2, l3);
}

// ---------------- int8 split GEMM (128x64 tile, 256 thr, 3 CTAs/SM) ----------
// Row mapping: A global row = (bm + r) * rmul + aoff
//   proj (mode 0): rmul=8, aoff=t  (A = g_xs, x-rows)  M-space = windows
//   rec  (mode 1): rmul=1, aoff=0  (A = h buffer)
// Single accumulator with a phase fold:
//   chunks 0..7  : acc += a1*w1           (D1)
//   after c==7   : acc *= 128             (fold; |acc|<1.06e9)
//   chunks 8..23 : acc += a1*w0 + a0*w1   (D2)
// dot = sc * acc
// mode 0: g_pre[(m*8+t)] = dot + bias; if t==0 also write quantized H0
// mode 1: h = tanh(dot + pre[(m*8+t)]); quantized h out (fp32 out at t=7)
__global__ __launch_bounds__(256, 3)
void gemm_s8x3(const int8_t* __restrict__ A,
               const int8_t* __restrict__ Bw,
               const float* __restrict__ b0, const float* __restrict__ b1,
               float* __restrict__ outp, int8_t* __restrict__ hs_out,
               int8_t* __restrict__ h0_out,
               float sc, int mode, int t, int rmul)
{
    extern __shared__ __align__(16) char dyn[];   // NSTAGE x [A:10240 | B:5120]
    __shared__ float s_bias[64];

    const int tid = threadIdx.x;
    const int wid = tid >> 5;
    const int lane = tid & 31;
    const int warpM = wid & 3;            // 4 warps along M (32 each)
    const int warpN = wid >> 2;           // 2 warps along N (32 each)
    const int bm = blockIdx.y * 128;
    const int bn = blockIdx.x * 64;
    const int aoff = (mode == 0) ? t : 0;

    const uint32_t sbase = smem_u32(dyn);

    if (mode == 0 && tid < 64) s_bias[tid] = b0[bn + tid] + b1[bn + tid];

    // Loaders: A tile 128x64B = 512 u4 (2/thread); B tile 64x64B = 256 u4 (1/thread)
    const int l_row0 = tid >> 2;            // 0..63
    const int l_row1 = l_row0 + 64;
    const int l_ch   = tid & 3;
    const uint4* A4 = (const uint4*)A;      // row stride 64 uint4 (1024 B)
    const uint4* B4 = (const uint4*)Bw;     // row stride 96 uint4 (1536 B)

    const uint32_t sA0 = l_row0 * ROWB + l_ch * 16;
    const uint32_t sA1 = l_row1 * ROWB + l_ch * 16;
    const uint4* Ap0 = &A4[((size_t)(bm + l_row0) * rmul + aoff) * 64 + l_ch];
    const uint4* Ap1 = &A4[((size_t)(bm + l_row1) * rmul + aoff) * 64 + l_ch];
    const uint4* Bp0 = &B4[(size_t)(bn + l_row0) * 96 + l_ch];

    // ldmatrix lane offsets
    const int g = lane >> 3;
    uint32_t a_off[2], b_off[2];
    #pragma unroll
    for (int mt = 0; mt < 2; mt++)
        a_off[mt] = (uint32_t)((warpM * 32 + mt * 16 + (g & 1) * 8 + (lane & 7)) * ROWB
                               + (g >> 1) * 16);
    #pragma unroll
    for (int np = 0; np < 2; np++)
        b_off[np] = (uint32_t)((warpN * 32 + np * 16 + (g >> 1) * 8 + (lane & 7)) * ROWB
                               + (g & 1) * 16);

    int32_t acc[2][4][4];
    #pragma unroll
    for (int i = 0; i < 2; i++)
        #pragma unroll
        for (int j = 0; j < 4; j++)
            #pragma unroll
            for (int q = 0; q < 4; q++) acc[i][j][q] = 0;

    // ---- prologue: fill stages 0..NSTAGE-2 (chunks 0..2, all < 8)
    #pragma unroll
    for (int s = 0; s < NSTAGE - 1; s++) {
        const uint32_t st = sbase + s * STAGEB;
        cp16(st + sA0,          Ap0 + s * 4);
        cp16(st + sA1,          Ap1 + s * 4);
        cp16(st + ATILEB + sA0, Bp0 + s * 4);
        cp_commit();
    }

    int st_cur = 0, st_nxt = NSTAGE - 1;
    for (int c = 0; c < NKIT; c++) {
        cp_wait<NSTAGE - 2>();
        __syncthreads();

        const int cn = c + NSTAGE - 1;
        if (cn < NKIT) {
            const uint32_t st = sbase + st_nxt * STAGEB;
            const int ka = (cn < 8 ? cn : cn - 8) * 4;
            cp16(st + sA0,          Ap0 + ka);
            cp16(st + sA1,          Ap1 + ka);
            cp16(st + ATILEB + sA0, Bp0 + cn * 4);
        }
        cp_commit();
        if (++st_nxt == NSTAGE) st_nxt = 0;

        const uint32_t ab = sbase + st_cur * STAGEB;
        const uint32_t bb = ab + ATILEB;
        if (++st_cur == NSTAGE) st_cur = 0;

        #pragma unroll
        for (int kk = 0; kk < 2; kk++) {
            uint32_t afr[2][4];
            uint32_t bfr[2][4];
            #pragma unroll
            for (int mt = 0; mt < 2; mt++)
                ldsm4(afr[mt][0], afr[mt][1], afr[mt][2], afr[mt][3],
                      ab + a_off[mt] + kk * 32);
            #pragma unroll
            for (int np = 0; np < 2; np++)
                ldsm4(bfr[np][0], bfr[np][1], bfr[np][2], bfr[np][3],
                      bb + b_off[np] + kk * 32);
            #pragma unroll
            for (int np = 0; np < 2; np++)
                #pragma unroll
                for (int mt = 0; mt < 2; mt++) {
                    mma16832(acc[mt][np * 2],     afr[mt], bfr[np][0], bfr[np][1]);
                    mma16832(acc[mt][np * 2 + 1], afr[mt], bfr[np][2], bfr[np][3]);
                }
        }

        if (c == 7) {   // phase fold: D1 complete -> scale by 128, continue with D2
            #pragma unroll
            for (int i = 0; i < 2; i++)
                #pragma unroll
                for (int j = 0; j < 4; j++)
                    #pragma unroll
                    for (int q = 0; q < 4; q++) acc[i][j][q] *= 128;
        }
    }

    // ---- epilogue --------------------------------------------------------
    const int r_in = lane >> 2;
    const int c_in = (lane & 3) * 2;
    #pragma unroll
    for (int mt = 0; mt < 2; mt++) {
        const int m0 = bm + warpM * 32 + mt * 16 + r_in;   // and m0+8
        #pragma unroll
        for (int nt = 0; nt < 4; nt++) {
            const int nb = bn + warpN * 32 + nt * 8 + c_in;
            float v00 = (float)acc[mt][nt][0] * sc;
            float v01 = (float)acc[mt][nt][1] * sc;
            float v10 = (float)acc[mt][nt][2] * sc;
            float v11 = (float)acc[mt][nt][3] * sc;
            if (mode == 0) {
                const float bia0 = s_bias[nb - bn], bia1 = s_bias[nb - bn + 1];
                v00 += bia0; v01 += bia1; v10 += bia0; v11 += bia1;
                *(float2*)(g_pre + ((size_t)m0 * 8 + t) * EDIM + nb)       = make_float2(v00, v01);
                *(float2*)(g_pre + ((size_t)(m0 + 8) * 8 + t) * EDIM + nb) = make_float2(v10, v11);
                if (t == 0) {
                    #pragma unroll
                    for (int h = 0; h < 2; h++) {
                        const size_t w = (size_t)(m0 + 8 * h);
                        float a0 = tanhf(h ? v10 : v00);
                        float a1 = tanhf(h ? v11 : v01);
                        int8_t x0,x1,y0,y1;
                        quant15(a0, 16384.0f, x0, y0);
                        quant15(a1, 16384.0f, x1, y1);
                        int8_t* hd = h0_out + w * KSTORE + nb;
                        *(char2*)(hd)       = make_char2(x0, x1);
                        *(char2*)(hd + 512) = make_char2(y0, y1);
                    }
                }
            } else {
                #pragma unroll
                for (int h = 0; h < 2; h++) {
                    const int m = m0 + 8 * h;
                    float2 pr = *(const float2*)(g_pre + ((size_t)m * TSTEPS + t) * EDIM + nb);
                    float a0 = tanhf((h ? v10 : v00) + pr.x);
                    float a1 = tanhf((h ? v11 : v01) + pr.y);
                    if (t == TSTEPS - 1) {
                        *(float2*)(outp + (size_t)m * EDIM + nb) = make_float2(a0, a1);
                    } else {
                        int8_t x0,x1,y0,y1;
                        quant15(a0, 16384.0f, x0, y0);
                        quant15(a1, 16384.0f, x1, y1);
                        int8_t* hd = hs_out + (size_t)m * KSTORE + nb;
                        *(char2*)(hd)       = make_char2(x0, x1);
                        *(char2*)(hd + 512) = make_char2(y0, y1);
                    }
                }
            }
        }
    }
}

// ---------------- host ------------------------------------------------------
extern "C" void kernel_launch(void* const* d_in, const int* in_sizes, int n_in,
                              void* d_out, int out_size)
{
    (void)in_sizes; (void)n_in; (void)out_size;
    const float* x    = (const float*)d_in[0];
    const float* W_ih = (const float*)d_in[1];
    const float* W_hh = (const float*)d_in[2];
    const float* b_ih = (const float*)d_in[3];
    const float* b_hh = (const float*)d_in[4];
    float* out = (float*)d_out;

    static int8_t* p_xs = nullptr;
    static int8_t* p_ws[2];
    static int8_t* p_hs[2];
    static cudaStream_t s2;
    static cudaEvent_t eP, eT[TSTEPS];
    if (!p_xs) {
        void* p;
        cudaGetSymbolAddress(&p, g_xs); p_xs = (int8_t*)p;
        cudaGetSymbolAddress(&p, g_ws);
        p_ws[0] = (int8_t*)p;
        p_ws[1] = p_ws[0] + (size_t)EDIM * KSPLIT;
        cudaGetSymbolAddress(&p, g_hs);
        p_hs[0] = (int8_t*)p;
        p_hs[1] = p_hs[0] + (size_t)NWIN * KSTORE;
        cudaFuncSetAttribute(gemm_s8x3,
                             cudaFuncAttributeMaxDynamicSharedMemorySize, SMEMB);
        cudaStreamCreateWithFlags(&s2, cudaStreamNonBlocking);
        cudaEventCreateWithFlags(&eP, cudaEventDisableTiming);
        for (int t = 0; t < TSTEPS; t++)
            cudaEventCreateWithFlags(&eT[t], cudaEventDisableTiming);
    }

    const dim3 gtile(8, 64);   // 512 CTAs: M=8192 windows x N=512

    // main stream: preps
    prep_w<<<2048, 256>>>(W_ih, W_hh);
    prep_x<<<32768, 256>>>(x);
    cudaEventRecord(eP, 0);

    // fork: side stream runs proj t2..t7, each with its own completion event
    cudaStreamWaitEvent(s2, eP, 0);
    for (int t = 2; t < TSTEPS; t++) {
        gemm_s8x3<<<gtile, 256, SMEMB, s2>>>(p_xs, p_ws[0], b_ih, b_hh,
                                             nullptr, nullptr, p_hs[0],
                                             SC_PROJ, 0, t, 8);
        cudaEventRecord(eT[t], s2);
    }

    // main: proj t0 (writes h0) and t1
    gemm_s8x3<<<gtile, 256, SMEMB>>>(p_xs, p_ws[0], b_ih, b_hh,
                                     nullptr, nullptr, p_hs[0],
                                     SC_PROJ, 0, 0, 8);
    gemm_s8x3<<<gtile, 256, SMEMB>>>(p_xs, p_ws[0], b_ih, b_hh,
                                     nullptr, nullptr, p_hs[0],
                                     SC_PROJ, 0, 1, 8);

    // recurrence: step t joins proj_t's event (t>=2) then runs on main stream
    for (int t = 1; t < TSTEPS; t++) {
        if (t >= 2) cudaStreamWaitEvent(0, eT[t], 0);
        gemm_s8x3<<<gtile, 256, SMEMB>>>(
            p_hs[(t - 1) & 1], p_ws[1], nullptr, nullptr,
            (t == TSTEPS - 1) ? out : nullptr, p_hs[t & 1], nullptr,
            SC_REC, 1, t, 1);
    }
}

// round 15
// speedup vs baseline: 1.4923x; 1.0405x over previous
#include <cuda_runtime.h>
#include <cuda_bf16.h>
#include <cstdint>
#include <math.h>

#define EDIM   512
#define TSTEPS 8
#define NWIN   8192
#define XROWS  65536
#define KSTORE 1024            // A/H stored int8: [limb1(512) | limb0(512)]
#define KSPLIT 1536            // W stored int8:  [w1(512) | w0(512) | w1(512)]
#define NKIT   24              // 1536 int8-K / 64 per chunk
#define ROWB   80              // smem row stride (64B data + 16B pad)
#define ATILEB (128 * ROWB)    // 10240
#define BTILEB (64 * ROWB)     // 5120
#define STAGEB (ATILEB + BTILEB)   // 15360
#define NSTAGE 4
#define SMEMB  (NSTAGE * STAGEB)   // 61440  (x3 CTAs = 184320)

#define SC_PROJ (1.0f / 4194304.0f)    // 2^-11 * 2^-18 * 128
#define SC_REC  (1.0f / 33554432.0f)   // 2^-14 * 2^-18 * 128

// ---------------- scratch ----------------------------------------------------
__device__ int8_t g_xs[(size_t)XROWS * KSTORE];      // 67 MB
__device__ int8_t g_ws[2][(size_t)EDIM * KSPLIT];    // 2 x 0.75 MB
__device__ int8_t g_hs[2][(size_t)NWIN * KSTORE];    // 2 x 8.4 MB
__device__ float  g_pre[(size_t)XROWS * EDIM];       // 134 MB

// ---------------- helpers ----------------------------------------------------
__device__ __forceinline__ uint32_t smem_u32(const void* p) {
    uint32_t a;
    asm("{ .reg .u64 t; cvta.to.shared.u64 t, %1; cvt.u32.u64 %0, t; }"
        : "=r"(a) : "l"(p));
    return a;
}
__device__ __forceinline__ void cp16(uint32_t saddr, const void* gaddr) {
    asm volatile("cp.async.cg.shared.global [%0], [%1], 16;"
                 :: "r"(saddr), "l"(gaddr) : "memory");
}
__device__ __forceinline__ void cp_commit() {
    asm volatile("cp.async.commit_group;" ::: "memory");
}
template <int N>
__device__ __forceinline__ void cp_wait() {
    asm volatile("cp.async.wait_group %0;" :: "n"(N) : "memory");
}
__device__ __forceinline__ void ldsm4(uint32_t& r0, uint32_t& r1, uint32_t& r2,
                                      uint32_t& r3, uint32_t addr) {
    asm volatile("ldmatrix.sync.aligned.m8n8.x4.shared.b16 {%0,%1,%2,%3}, [%4];"
                 : "=r"(r0), "=r"(r1), "=r"(r2), "=r"(r3) : "r"(addr));
}
__device__ __forceinline__ void mma16832(int32_t* c, const uint32_t* a,
                                         uint32_t b0, uint32_t b1) {
    asm volatile("mma.sync.aligned.m16n8k32.row.col.s32.s8.s8.s32 "
                 "{%0,%1,%2,%3}, {%4,%5,%6,%7}, {%8,%9}, {%0,%1,%2,%3};"
                 : "+r"(c[0]), "+r"(c[1]), "+r"(c[2]), "+r"(c[3])
                 : "r"(a[0]), "r"(a[1]), "r"(a[2]), "r"(a[3]), "r"(b0), "r"(b1));
}
// Rounded fixed-point split: v*scale -> 15-bit int -> two int8 limbs,
// residual in [-64, 63] (zero-mean).
__device__ __forceinline__ void quant15(float v, float scale, int8_t& hi, int8_t& lo) {
    int xi = __float2int_rn(v * scale);
    xi = max(-16320, min(16319, xi));
    int h = (xi + 64) >> 7;
    hi = (int8_t)h;
    lo = (int8_t)(xi - (h << 7));
}

// ---------------- prep kernels ----------------------------------------------
__global__ __launch_bounds__(256)
void prep_w(const float* __restrict__ wih, const float* __restrict__ whh) {
    int idx = blockIdx.x * 256 + threadIdx.x;           // 0 .. 2*512*512-1
    int which = idx >> 18;
    int e = idx & 262143;
    int n = e >> 9, k = e & 511;
    const float* src = which ? whh : wih;
    int8_t w1, w0;
    quant15(src[n * 512 + k], 262144.0f, w1, w0);       // 2^18
    int8_t* dst = g_ws[which] + (size_t)n * KSPLIT;
    dst[k] = w1; dst[512 + k] = w0; dst[1024 + k] = w1;
}

// Per-t slice of x quantization: rows w*8+t for all windows w.
__global__ __launch_bounds__(256)
void prep_x_t(const float* __restrict__ x, int t) {
    size_t idx = (size_t)blockIdx.x * 256 + threadIdx.x;  // 8192*128 float4
    size_t w = idx >> 7;
    int q = (int)(idx & 127);
    size_t row = w * TSTEPS + t;
    float4 v = ((const float4*)x)[row * 128 + q];
    int8_t h0,h1,h2,h3,l0,l1,l2,l3;
    quant15(v.x, 2048.0f, h0, l0);                      // 2^11
    quant15(v.y, 2048.0f, h1, l1);
    quant15(v.z, 2048.0f, h2, l2);
    quant15(v.w, 2048.0f, h3, l3);
    int8_t* base = g_xs + row * KSTORE + q * 4;
    *(char4*)(base)       = make_char4(h0, h1, h2, h3);
    *(char4*)(base + 512) = make_char4(l0, l1, l2, l3);
}

// ---------------- int8 split GEMM (128x64 tile, 256 thr, 3 CTAs/SM) ----------
// Row mapping: A global row = (bm + r) * rmul + aoff
//   proj (mode 0): rmul=8, aoff=t  (A = g_xs)   M-space = windows
//   rec  (mode 1): rmul=1, aoff=0  (A = h buffer)
// Single accumulator with a phase fold:
//   chunks 0..7  : acc += a1*w1           (D1)
//   after c==7   : acc *= 128             (fold; |acc|<1.06e9)
//   chunks 8..23 : acc += a1*w0 + a0*w1   (D2)
// dot = sc * acc
// mode 0: g_pre[(m*8+t)] = dot + bias; if t==0 also write quantized H0
// mode 1: h = tanh(dot + pre[(m*8+t)]); quantized h out (fp32 out at t=7)
__global__ __launch_bounds__(256, 3)
void gemm_s8x3(const int8_t* __restrict__ A,
               const int8_t* __restrict__ Bw,
               const float* __restrict__ b0, const float* __restrict__ b1,
               float* __restrict__ outp, int8_t* __restrict__ hs_out,
               int8_t* __restrict__ h0_out,
               float sc, int mode, int t, int rmul)
{
    extern __shared__ __align__(16) char dyn[];   // NSTAGE x [A:10240 | B:5120]
    __shared__ float s_bias[64];

    const int tid = threadIdx.x;
    const int wid = tid >> 5;
    const int lane = tid & 31;
    const int warpM = wid & 3;            // 4 warps along M (32 each)
    const int warpN = wid >> 2;           // 2 warps along N (32 each)
    const int bm = blockIdx.y * 128;
    const int bn = blockIdx.x * 64;
    const int aoff = (mode == 0) ? t : 0;

    const uint32_t sbase = smem_u32(dyn);

    if (mode == 0 && tid < 64) s_bias[tid] = b0[bn + tid] + b1[bn + tid];

    // Loaders: A tile 128x64B = 512 u4 (2/thread); B tile 64x64B = 256 u4 (1/thread)
    const int l_row0 = tid >> 2;            // 0..63
    const int l_row1 = l_row0 + 64;
    const int l_ch   = tid & 3;
    const uint4* A4 = (const uint4*)A;      // row stride 64 uint4 (1024 B)
    const uint4* B4 = (const uint4*)Bw;     // row stride 96 uint4 (1536 B)

    const uint32_t sA0 = l_row0 * ROWB + l_ch * 16;
    const uint32_t sA1 = l_row1 * ROWB + l_ch * 16;
    const uint4* Ap0 = &A4[((size_t)(bm + l_row0) * rmul + aoff) * 64 + l_ch];
    const uint4* Ap1 = &A4[((size_t)(bm + l_row1) * rmul + aoff) * 64 + l_ch];
    const uint4* Bp0 = &B4[(size_t)(bn + l_row0) * 96 + l_ch];

    // ldmatrix lane offsets
    const int g = lane >> 3;
    uint32_t a_off[2], b_off[2];
    #pragma unroll
    for (int mt = 0; mt < 2; mt++)
        a_off[mt] = (uint32_t)((warpM * 32 + mt * 16 + (g & 1) * 8 + (lane & 7)) * ROWB
                               + (g >> 1) * 16);
    #pragma unroll
    for (int np = 0; np < 2; np++)
        b_off[np] = (uint32_t)((warpN * 32 + np * 16 + (g >> 1) * 8 + (lane & 7)) * ROWB
                               + (g & 1) * 16);

    int32_t acc[2][4][4];
    #pragma unroll
    for (int i = 0; i < 2; i++)
        #pragma unroll
        for (int j = 0; j < 4; j++)
            #pragma unroll
            for (int q = 0; q < 4; q++) acc[i][j][q] = 0;

    // ---- prologue: fill stages 0..NSTAGE-2 (chunks 0..2, all < 8)
    #pragma unroll
    for (int s = 0; s < NSTAGE - 1; s++) {
        const uint32_t st = sbase + s * STAGEB;
        cp16(st + sA0,          Ap0 + s * 4);
        cp16(st + sA1,          Ap1 + s * 4);
        cp16(st + ATILEB + sA0, Bp0 + s * 4);
        cp_commit();
    }

    int st_cur = 0, st_nxt = NSTAGE - 1;
    for (int c = 0; c < NKIT; c++) {
        cp_wait<NSTAGE - 2>();
        __syncthreads();

        const int cn = c + NSTAGE - 1;
        if (cn < NKIT) {
            const uint32_t st = sbase + st_nxt * STAGEB;
            const int ka = (cn < 8 ? cn : cn - 8) * 4;
            cp16(st + sA0,          Ap0 + ka);
            cp16(st + sA1,          Ap1 + ka);
            cp16(st + ATILEB + sA0, Bp0 + cn * 4);
        }
        cp_commit();
        if (++st_nxt == NSTAGE) st_nxt = 0;

        const uint32_t ab = sbase + st_cur * STAGEB;
        const uint32_t bb = ab + ATILEB;
        if (++st_cur == NSTAGE) st_cur = 0;

        #pragma unroll
        for (int kk = 0; kk < 2; kk++) {
            uint32_t afr[2][4];
            uint32_t bfr[2][4];
            #pragma unroll
            for (int mt = 0; mt < 2; mt++)
                ldsm4(afr[mt][0], afr[mt][1], afr[mt][2], afr[mt][3],
                      ab + a_off[mt] + kk * 32);
            #pragma unroll
            for (int np = 0; np < 2; np++)
                ldsm4(bfr[np][0], bfr[np][1], bfr[np][2], bfr[np][3],
                      bb + b_off[np] + kk * 32);
            #pragma unroll
            for (int np = 0; np < 2; np++)
                #pragma unroll
                for (int mt = 0; mt < 2; mt++) {
                    mma16832(acc[mt][np * 2],     afr[mt], bfr[np][0], bfr[np][1]);
                    mma16832(acc[mt][np * 2 + 1], afr[mt], bfr[np][2], bfr[np][3]);
                }
        }

        if (c == 7) {   // phase fold: D1 complete -> scale by 128, continue with D2
            #pragma unroll
            for (int i = 0; i < 2; i++)
                #pragma unroll
                for (int j = 0; j < 4; j++)
                    #pragma unroll
                    for (int q = 0; q < 4; q++) acc[i][j][q] *= 128;
        }
    }

    // ---- epilogue --------------------------------------------------------
    const int r_in = lane >> 2;
    const int c_in = (lane & 3) * 2;
    #pragma unroll
    for (int mt = 0; mt < 2; mt++) {
        const int m0 = bm + warpM * 32 + mt * 16 + r_in;   // and m0+8
        #pragma unroll
        for (int nt = 0; nt < 4; nt++) {
            const int nb = bn + warpN * 32 + nt * 8 + c_in;
            float v00 = (float)acc[mt][nt][0] * sc;
            float v01 = (float)acc[mt][nt][1] * sc;
            float v10 = (float)acc[mt][nt][2] * sc;
            float v11 = (float)acc[mt][nt][3] * sc;
            if (mode == 0) {
                const float bia0 = s_bias[nb - bn], bia1 = s_bias[nb - bn + 1];
                v00 += bia0; v01 += bia1; v10 += bia0; v11 += bia1;
                *(float2*)(g_pre + ((size_t)m0 * 8 + t) * EDIM + nb)       = make_float2(v00, v01);
                *(float2*)(g_pre + ((size_t)(m0 + 8) * 8 + t) * EDIM + nb) = make_float2(v10, v11);
                if (t == 0) {
                    #pragma unroll
                    for (int h = 0; h < 2; h++) {
                        const size_t w = (size_t)(m0 + 8 * h);
                        float a0 = tanhf(h ? v10 : v00);
                        float a1 = tanhf(h ? v11 : v01);
                        int8_t x0,x1,y0,y1;
                        quant15(a0, 16384.0f, x0, y0);
                        quant15(a1, 16384.0f, x1, y1);
                        int8_t* hd = h0_out + w * KSTORE + nb;
                        *(char2*)(hd)       = make_char2(x0, x1);
                        *(char2*)(hd + 512) = make_char2(y0, y1);
                    }
                }
            } else {
                #pragma unroll
                for (int h = 0; h < 2; h++) {
                    const int m = m0 + 8 * h;
                    float2 pr = *(const float2*)(g_pre + ((size_t)m * TSTEPS + t) * EDIM + nb);
                    float a0 = tanhf((h ? v10 : v00) + pr.x);
                    float a1 = tanhf((h ? v11 : v01) + pr.y);
                    if (t == TSTEPS - 1) {
                        *(float2*)(outp + (size_t)m * EDIM + nb) = make_float2(a0, a1);
                    } else {
                        int8_t x0,x1,y0,y1;
                        quant15(a0, 16384.0f, x0, y0);
                        quant15(a1, 16384.0f, x1, y1);
                        int8_t* hd = hs_out + (size_t)m * KSTORE + nb;
                        *(char2*)(hd)       = make_char2(x0, x1);
                        *(char2*)(hd + 512) = make_char2(y0, y1);
                    }
                }
            }
        }
    }
}

// ---------------- host ------------------------------------------------------
extern "C" void kernel_launch(void* const* d_in, const int* in_sizes, int n_in,
                              void* d_out, int out_size)
{
    (void)in_sizes; (void)n_in; (void)out_size;
    const float* x    = (const float*)d_in[0];
    const float* W_ih = (const float*)d_in[1];
    const float* W_hh = (const float*)d_in[2];
    const float* b_ih = (const float*)d_in[3];
    const float* b_hh = (const float*)d_in[4];
    float* out = (float*)d_out;

    static int8_t* p_xs = nullptr;
    static int8_t* p_ws[2];
    static int8_t* p_hs[2];
    static cudaStream_t s2;
    static cudaEvent_t eX[TSTEPS], eT[TSTEPS];
    if (!p_xs) {
        void* p;
        cudaGetSymbolAddress(&p, g_xs); p_xs = (int8_t*)p;
        cudaGetSymbolAddress(&p, g_ws);
        p_ws[0] = (int8_t*)p;
        p_ws[1] = p_ws[0] + (size_t)EDIM * KSPLIT;
        cudaGetSymbolAddress(&p, g_hs);
        p_hs[0] = (int8_t*)p;
        p_hs[1] = p_hs[0] + (size_t)NWIN * KSTORE;
        cudaFuncSetAttribute(gemm_s8x3,
                             cudaFuncAttributeMaxDynamicSharedMemorySize, SMEMB);
        cudaStreamCreateWithFlags(&s2, cudaStreamNonBlocking);
        for (int t = 0; t < TSTEPS; t++) {
            cudaEventCreateWithFlags(&eX[t], cudaEventDisableTiming);
            cudaEventCreateWithFlags(&eT[t], cudaEventDisableTiming);
        }
    }

    const dim3 gtile(8, 64);   // 512 CTAs: M=8192 windows x N=512

    // main: weight prep, then x-quant slices (memory-bound) with per-t events
    prep_w<<<2048, 256>>>(W_ih, W_hh);
    for (int t = 0; t < TSTEPS; t++) {
        prep_x_t<<<4096, 256>>>(x, t);
        cudaEventRecord(eX[t], 0);
    }

    // side stream: all 8 projections, each gated on its x-slice
    for (int t = 0; t < TSTEPS; t++) {
        cudaStreamWaitEvent(s2, eX[t], 0);
        gemm_s8x3<<<gtile, 256, SMEMB, s2>>>(p_xs, p_ws[0], b_ih, b_hh,
                                             nullptr, nullptr, p_hs[0],
                                             SC_PROJ, 0, t, 8);
        cudaEventRecord(eT[t], s2);
    }

    // main: recurrence; step t joins proj_t (and step 1 additionally proj_0/h0)
    cudaStreamWaitEvent(0, eT[0], 0);
    for (int t = 1; t < TSTEPS; t++) {
        cudaStreamWaitEvent(0, eT[t], 0);
        gemm_s8x3<<<gtile, 256, SMEMB>>>(
            p_hs[(t - 1) & 1], p_ws[1], nullptr, nullptr,
            (t == TSTEPS - 1) ? out : nullptr, p_hs[t & 1], nullptr,
            SC_REC, 1, t, 1);
    }
}

// round 17
// speedup vs baseline: 2.1628x; 1.4494x over previous
#include <cuda_runtime.h>
#include <cuda_fp16.h>
#include <cstdint>
#include <math.h>

#define EDIM   512
#define TSTEPS 8
#define NWIN   8192
#define XROWS  65536
#define NKIT   16              // 512 K / 32 per chunk
#define ROWB   80              // smem row stride (64B data + 16B pad)
#define ATILEB (128 * ROWB)    // 10240
#define BTILEB (64 * ROWB)     // 5120
#define STAGEB (ATILEB + BTILEB)   // 15360
#define NSTAGE 4
#define SMEMB  (NSTAGE * STAGEB)   // 61440  (x3 CTAs = 184320)

// ---------------- scratch ----------------------------------------------------
__device__ __half g_xs[(size_t)XROWS * EDIM];        // 67 MB
__device__ __half g_ws[2][(size_t)EDIM * EDIM];      // 2 x 0.5 MB
__device__ __half g_hs[2][(size_t)NWIN * EDIM];      // 2 x 8.4 MB
__device__ float  g_pre[(size_t)XROWS * EDIM];       // 134 MB

// ---------------- helpers ----------------------------------------------------
__device__ __forceinline__ uint32_t smem_u32(const void* p) {
    uint32_t a;
    asm("{ .reg .u64 t; cvta.to.shared.u64 t, %1; cvt.u32.u64 %0, t; }"
        : "=r"(a) : "l"(p));
    return a;
}
__device__ __forceinline__ void cp16(uint32_t saddr, const void* gaddr) {
    asm volatile("cp.async.cg.shared.global [%0], [%1], 16;"
                 :: "r"(saddr), "l"(gaddr) : "memory");
}
__device__ __forceinline__ void cp_commit() {
    asm volatile("cp.async.commit_group;" ::: "memory");
}
template <int N>
__device__ __forceinline__ void cp_wait() {
    asm volatile("cp.async.wait_group %0;" :: "n"(N) : "memory");
}
__device__ __forceinline__ void ldsm4(uint32_t& r0, uint32_t& r1, uint32_t& r2,
                                      uint32_t& r3, uint32_t addr) {
    asm volatile("ldmatrix.sync.aligned.m8n8.x4.shared.b16 {%0,%1,%2,%3}, [%4];"
                 : "=r"(r0), "=r"(r1), "=r"(r2), "=r"(r3) : "r"(addr));
}
__device__ __forceinline__ void mma16816f(float* c, const uint32_t* a,
                                          uint32_t b0, uint32_t b1) {
    asm volatile("mma.sync.aligned.m16n8k16.row.col.f32.f16.f16.f32 "
                 "{%0,%1,%2,%3}, {%4,%5,%6,%7}, {%8,%9}, {%0,%1,%2,%3};"
                 : "+f"(c[0]), "+f"(c[1]), "+f"(c[2]), "+f"(c[3])
                 : "r"(a[0]), "r"(a[1]), "r"(a[2]), "r"(a[3]), "r"(b0), "r"(b1));
}

// ---------------- prep kernels ----------------------------------------------
__global__ __launch_bounds__(256)
void prep_w(const float* __restrict__ wih, const float* __restrict__ whh) {
    int idx = blockIdx.x * 256 + threadIdx.x;           // 0 .. 2*512*512-1
    int which = idx >> 18;
    int e = idx & 262143;
    const float* src = which ? whh : wih;
    g_ws[which][e] = __float2half(src[e]);
}

// Per-t slice of x conversion: rows w*8+t for all windows w.
__global__ __launch_bounds__(256)
void prep_x_t(const float* __restrict__ x, int t) {
    size_t idx = (size_t)blockIdx.x * 256 + threadIdx.x;  // 8192*128 float4
    size_t w = idx >> 7;
    int q = (int)(idx & 127);
    size_t row = w * TSTEPS + t;
    float4 v = ((const float4*)x)[row * 128 + q];
    __half2 h01 = __floats2half2_rn(v.x, v.y);
    __half2 h23 = __floats2half2_rn(v.z, v.w);
    __half* base = g_xs + row * EDIM + q * 4;
    *(__half2*)(base)     = h01;
    *(__half2*)(base + 2) = h23;
}

// ---------------- fp16 GEMM (128x64 tile, 256 thr, 3 CTAs/SM) ----------------
// C[m][n] = sum_k A[m][k] * W[n][k]   (K=512 fp16, fp32 accum)
// Row mapping: A global row = (bm + r) * rmul + aoff
//   proj (mode 0): rmul=8, aoff=t  (A = g_xs)   M-space = windows
//   rec  (mode 1): rmul=1, aoff=0  (A = h buffer)
// mode 0: g_pre[(m*8+t)] = acc + bias; if t==0 also write fp16 H0 = tanh(...)
// mode 1: h = tanh(acc + pre[(m*8+t)]); fp16 h out (fp32 out at t=7)
__global__ __launch_bounds__(256, 3)
void gemm_f16(const __half* __restrict__ A,
              const __half* __restrict__ Bw,
              const float* __restrict__ b0, const float* __restrict__ b1,
              float* __restrict__ outp, __half* __restrict__ hs_out,
              __half* __restrict__ h0_out,
              int mode, int t, int rmul)
{
    extern __shared__ __align__(16) char dyn[];   // NSTAGE x [A:10240 | B:5120]
    __shared__ float s_bias[64];

    const int tid = threadIdx.x;
    const int wid = tid >> 5;
    const int lane = tid & 31;
    const int warpM = wid & 3;            // 4 warps along M (32 each)
    const int warpN = wid >> 2;           // 2 warps along N (32 each)
    const int bm = blockIdx.y * 128;
    const int bn = blockIdx.x * 64;
    const int aoff = (mode == 0) ? t : 0;

    const uint32_t sbase = smem_u32(dyn);

    if (mode == 0 && tid < 64) s_bias[tid] = b0[bn + tid] + b1[bn + tid];

    // Loaders: A tile 128 rows x 64B = 512 u4 (2/thread); B tile 64 rows (1/thread)
    const int l_row0 = tid >> 2;            // 0..63
    const int l_row1 = l_row0 + 64;
    const int l_ch   = tid & 3;
    const uint4* A4 = (const uint4*)A;      // row stride 64 uint4 (1024 B)
    const uint4* B4 = (const uint4*)Bw;     // row stride 64 uint4 (1024 B)

    const uint32_t sA0 = l_row0 * ROWB + l_ch * 16;
    const uint32_t sA1 = l_row1 * ROWB + l_ch * 16;
    const uint4* Ap0 = &A4[((size_t)(bm + l_row0) * rmul + aoff) * 64 + l_ch];
    const uint4* Ap1 = &A4[((size_t)(bm + l_row1) * rmul + aoff) * 64 + l_ch];
    const uint4* Bp0 = &B4[(size_t)(bn + l_row0) * 64 + l_ch];

    // ldmatrix lane offsets (same geometry as verified bf16/int8 kernels)
    const int g = lane >> 3;
    uint32_t a_off[2], b_off[2];
    #pragma unroll
    for (int mt = 0; mt < 2; mt++)
        a_off[mt] = (uint32_t)((warpM * 32 + mt * 16 + (g & 1) * 8 + (lane & 7)) * ROWB
                               + (g >> 1) * 16);
    #pragma unroll
    for (int np = 0; np < 2; np++)
        b_off[np] = (uint32_t)((warpN * 32 + np * 16 + (g >> 1) * 8 + (lane & 7)) * ROWB
                               + (g & 1) * 16);

    float acc[2][4][4];
    #pragma unroll
    for (int i = 0; i < 2; i++)
        #pragma unroll
        for (int j = 0; j < 4; j++)
            #pragma unroll
            for (int q = 0; q < 4; q++) acc[i][j][q] = 0.0f;

    // ---- prologue: fill stages 0..NSTAGE-2
    #pragma unroll
    for (int s = 0; s < NSTAGE - 1; s++) {
        const uint32_t st = sbase + s * STAGEB;
        cp16(st + sA0,          Ap0 + s * 4);
        cp16(st + sA1,          Ap1 + s * 4);
        cp16(st + ATILEB + sA0, Bp0 + s * 4);
        cp_commit();
    }

    int st_cur = 0, st_nxt = NSTAGE - 1;
    for (int c = 0; c < NKIT; c++) {
        cp_wait<NSTAGE - 2>();
        __syncthreads();

        const int cn = c + NSTAGE - 1;
        if (cn < NKIT) {
            const uint32_t st = sbase + st_nxt * STAGEB;
            cp16(st + sA0,          Ap0 + cn * 4);
            cp16(st + sA1,          Ap1 + cn * 4);
            cp16(st + ATILEB + sA0, Bp0 + cn * 4);
        }
        cp_commit();
        if (++st_nxt == NSTAGE) st_nxt = 0;

        const uint32_t ab = sbase + st_cur * STAGEB;
        const uint32_t bb = ab + ATILEB;
        if (++st_cur == NSTAGE) st_cur = 0;

        #pragma unroll
        for (int kk = 0; kk < 2; kk++) {
            uint32_t afr[2][4];
            uint32_t bfr[2][4];
            #pragma unroll
            for (int mt = 0; mt < 2; mt++)
                ldsm4(afr[mt][0], afr[mt][1], afr[mt][2], afr[mt][3],
                      ab + a_off[mt] + kk * 32);
            #pragma unroll
            for (int np = 0; np < 2; np++)
                ldsm4(bfr[np][0], bfr[np][1], bfr[np][2], bfr[np][3],
                      bb + b_off[np] + kk * 32);
            #pragma unroll
            for (int np = 0; np < 2; np++)
                #pragma unroll
                for (int mt = 0; mt < 2; mt++) {
                    mma16816f(acc[mt][np * 2],     afr[mt], bfr[np][0], bfr[np][1]);
                    mma16816f(acc[mt][np * 2 + 1], afr[mt], bfr[np][2], bfr[np][3]);
                }
        }
    }

    // ---- epilogue --------------------------------------------------------
    const int r_in = lane >> 2;
    const int c_in = (lane & 3) * 2;
    #pragma unroll
    for (int mt = 0; mt < 2; mt++) {
        const int m0 = bm + warpM * 32 + mt * 16 + r_in;   // and m0+8
        #pragma unroll
        for (int nt = 0; nt < 4; nt++) {
            const int nb = bn + warpN * 32 + nt * 8 + c_in;
            float v00 = acc[mt][nt][0];
            float v01 = acc[mt][nt][1];
            float v10 = acc[mt][nt][2];
            float v11 = acc[mt][nt][3];
            if (mode == 0) {
                const float bia0 = s_bias[nb - bn], bia1 = s_bias[nb - bn + 1];
                v00 += bia0; v01 += bia1; v10 += bia0; v11 += bia1;
                *(float2*)(g_pre + ((size_t)m0 * 8 + t) * EDIM + nb)       = make_float2(v00, v01);
                *(float2*)(g_pre + ((size_t)(m0 + 8) * 8 + t) * EDIM + nb) = make_float2(v10, v11);
                if (t == 0) {
                    #pragma unroll
                    for (int h = 0; h < 2; h++) {
                        const size_t w = (size_t)(m0 + 8 * h);
                        float a0 = tanhf(h ? v10 : v00);
                        float a1 = tanhf(h ? v11 : v01);
                        *(__half2*)(h0_out + w * EDIM + nb) = __floats2half2_rn(a0, a1);
                    }
                }
            } else {
                #pragma unroll
                for (int h = 0; h < 2; h++) {
                    const int m = m0 + 8 * h;
                    float2 pr = *(const float2*)(g_pre + ((size_t)m * TSTEPS + t) * EDIM + nb);
                    float a0 = tanhf((h ? v10 : v00) + pr.x);
                    float a1 = tanhf((h ? v11 : v01) + pr.y);
                    if (t == TSTEPS - 1) {
                        *(float2*)(outp + (size_t)m * EDIM + nb) = make_float2(a0, a1);
                    } else {
                        *(__half2*)(hs_out + (size_t)m * EDIM + nb) = __floats2half2_rn(a0, a1);
                    }
                }
            }
        }
    }
}

// ---------------- host ------------------------------------------------------
extern "C" void kernel_launch(void* const* d_in, const int* in_sizes, int n_in,
                              void* d_out, int out_size)
{
    (void)in_sizes; (void)n_in; (void)out_size;
    const float* x    = (const float*)d_in[0];
    const float* W_ih = (const float*)d_in[1];
    const float* W_hh = (const float*)d_in[2];
    const float* b_ih = (const float*)d_in[3];
    const float* b_hh = (const float*)d_in[4];
    float* out = (float*)d_out;

    static __half* p_xs = nullptr;
    static __half* p_ws[2];
    static __half* p_hs[2];
    static cudaStream_t s2;
    static cudaEvent_t eX[TSTEPS], eT[TSTEPS];
    if (!p_xs) {
        void* p;
        cudaGetSymbolAddress(&p, g_xs); p_xs = (__half*)p;
        cudaGetSymbolAddress(&p, g_ws);
        p_ws[0] = (__half*)p;
        p_ws[1] = p_ws[0] + (size_t)EDIM * EDIM;
        cudaGetSymbolAddress(&p, g_hs);
        p_hs[0] = (__half*)p;
        p_hs[1] = p_hs[0] + (size_t)NWIN * EDIM;
        cudaFuncSetAttribute(gemm_f16,
                             cudaFuncAttributeMaxDynamicSharedMemorySize, SMEMB);
        cudaStreamCreateWithFlags(&s2, cudaStreamNonBlocking);
        for (int t = 0; t < TSTEPS; t++) {
            cudaEventCreateWithFlags(&eX[t], cudaEventDisableTiming);
            cudaEventCreateWithFlags(&eT[t], cudaEventDisableTiming);
        }
    }

    const dim3 gtile(8, 64);   // 512 CTAs: M=8192 windows x N=512

    // main: weight prep, then x-convert slices (memory-bound) with per-t events
    prep_w<<<2048, 256>>>(W_ih, W_hh);
    for (int t = 0; t < TSTEPS; t++) {
        prep_x_t<<<4096, 256>>>(x, t);
        cudaEventRecord(eX[t], 0);
    }

    // side stream: all 8 projections, each gated on its x-slice
    for (int t = 0; t < TSTEPS; t++) {
        cudaStreamWaitEvent(s2, eX[t], 0);
        gemm_f16<<<gtile, 256, SMEMB, s2>>>(p_xs, p_ws[0], b_ih, b_hh,
                                            nullptr, nullptr, p_hs[0],
                                            0, t, 8);
        cudaEventRecord(eT[t], s2);
    }

    // main: recurrence; step t joins proj_t (and step 1 additionally proj_0/h0)
    cudaStreamWaitEvent(0, eT[0], 0);
    for (int t = 1; t < TSTEPS; t++) {
        cudaStreamWaitEvent(0, eT[t], 0);
        gemm_f16<<<gtile, 256, SMEMB>>>(
            p_hs[(t - 1) & 1], p_ws[1], nullptr, nullptr,
            (t == TSTEPS - 1) ? out : nullptr, p_hs[t & 1], nullptr,
            1, t, 1);
    }
}